// round 2
// baseline (speedup 1.0000x reference)
#include <cuda_runtime.h>

#define LOG_SQRT_2PI 0.9189385332046727f

// Scalar prior, written by prior_kernel, read by mse_posterior_kernel
// (same-stream ordering inside the captured graph guarantees visibility).
__device__ float g_prior;

// ---------------------------------------------------------------------------
// Kernel A: prior = (1/B) * sum_{b,i} [ log(sqrt(2pi)) + log(sigma) + (pred-mu)^2/(2 sigma^2) ]
// One block; tiny data (448 KB). Branch logic matches the reference
// calculateExpectedValues exactly (mutually exclusive mask chain).
// ---------------------------------------------------------------------------
__global__ void prior_kernel(const float* __restrict__ pred,
                             const float* __restrict__ sigma,
                             int B) {
    float acc = 0.0f;
    for (int row = threadIdx.x; row < B; row += blockDim.x) {
        const float* p = pred + (size_t)row * 7;
        float O2  = p[0], N2 = p[1], H2 = p[2], CO2 = p[3];
        float H2O = p[4], CH4 = p[5], NH3 = p[6];

        float H = 2.0f*H2 + 2.0f*H2O + 3.0f*NH3 + 4.0f*CH4;
        float C = CO2 + CH4;
        float O = 2.0f*O2 + 2.0f*CO2 + H2O;
        float N = 2.0f*N2 + NH3;

        float mu0=0.f, mu1=0.f, mu2=0.f, mu3=0.f, mu4=0.f, mu5=0.f, mu6=0.f;

        bool condA = (H > 2.0f*O + 4.0f*C);
        if (condA) {
            if (3.0f*N < H - 2.0f*O - 4.0f*C) {
                // branch A1: D = H - N - 2C
                float inv = 1.0f / (H - N - 2.0f*C);
                mu2 = (H - 2.0f*O - 4.0f*C - 3.0f*N) * inv;
                mu4 = 2.0f*O * inv;
                mu5 = 2.0f*C * inv;
                mu6 = 2.0f*N * inv;
            } else {
                // branch A2: D = H + 2C + 3N + 4O
                float inv = 1.0f / (H + 2.0f*C + 3.0f*N + 4.0f*O);
                mu1 = (3.0f*N + 4.0f*C + 2.0f*O - H) * inv;
                mu4 = 6.0f*O * inv;
                mu5 = 6.0f*C * inv;
                mu6 = (2.0f*H - 8.0f*C - 4.0f*O) * inv;
            }
        } else if (2.0f*O > H + 4.0f*C) {
            // branch B: D = H + 2O + 2N
            float inv = 1.0f / (H + 2.0f*O + 2.0f*N);
            mu0 = (2.0f*O - H - 4.0f*C) * inv;
            mu1 = 2.0f*N * inv;
            mu3 = 4.0f*C * inv;
            mu4 = 2.0f*H * inv;
        } else if (fabsf(H + C + O + N - 1.0f) < 1e-3f) {
            // branch C: D1 = H + 2O + 2N, D2 = 2H + 4O + 4N
            float inv1 = 1.0f / (H + 2.0f*O + 2.0f*N);
            float inv2 = 1.0f / (2.0f*H + 4.0f*O + 4.0f*N);
            mu1 = 2.0f*N * inv1;
            mu3 = (2.0f*O + 4.0f*C - H) * inv2;
            mu4 = (H + 2.0f*O - 4.0f*C) * inv1;
            mu5 = (H - 2.0f*O + 4.0f*C) * inv2;
        }
        // else: unclassified -> mu = 0

        const float* s = sigma + (size_t)row * 7;
        float mu[7] = {mu0, mu1, mu2, mu3, mu4, mu5, mu6};
        #pragma unroll
        for (int i = 0; i < 7; i++) {
            float sg = s[i];
            float d  = p[i] - mu[i];
            acc += LOG_SQRT_2PI + logf(sg) + d*d / (2.0f * sg * sg);
        }
    }

    // Block reduction: warp shuffle -> smem -> warp shuffle
    __shared__ float warp_sums[32];
    #pragma unroll
    for (int off = 16; off; off >>= 1)
        acc += __shfl_down_sync(0xffffffffu, acc, off);
    int lane = threadIdx.x & 31;
    int wid  = threadIdx.x >> 5;
    if (lane == 0) warp_sums[wid] = acc;
    __syncthreads();
    if (wid == 0) {
        int nwarps = (blockDim.x + 31) >> 5;
        acc = (lane < nwarps) ? warp_sums[lane] : 0.0f;
        #pragma unroll
        for (int off = 16; off; off >>= 1)
            acc += __shfl_down_sync(0xffffffffu, acc, off);
        if (lane == 0) g_prior = acc / (float)B;
    }
}

// ---------------------------------------------------------------------------
// Kernel B: one block per batch row. Streaming MSE over S floats per input,
// float4-vectorized, fully coalesced, manually unrolled x2 (4 independent
// LDG.128 in flight per thread per iteration). posterior[b] = sum*scale+prior.
// ---------------------------------------------------------------------------
__global__ void mse_posterior_kernel(const float4* __restrict__ yR,
                                     const float4* __restrict__ yS,
                                     float* __restrict__ out,
                                     int Sv,        // S / 4 (# of float4 per row)
                                     float scale) {
    int row = blockIdx.x;
    const float4* r = yR + (size_t)row * Sv;
    const float4* s = yS + (size_t)row * Sv;

    float acc0 = 0.0f, acc1 = 0.0f;
    int stride = blockDim.x;
    int i = threadIdx.x;
    // Main unrolled-x2 loop: issue 4 independent 16B loads up front.
    for (; i + stride < Sv; i += 2 * stride) {
        float4 a0 = __ldg(&r[i]);
        float4 b0 = __ldg(&s[i]);
        float4 a1 = __ldg(&r[i + stride]);
        float4 b1 = __ldg(&s[i + stride]);
        float d;
        d = a0.x - b0.x; acc0 = fmaf(d, d, acc0);
        d = a0.y - b0.y; acc0 = fmaf(d, d, acc0);
        d = a0.z - b0.z; acc0 = fmaf(d, d, acc0);
        d = a0.w - b0.w; acc0 = fmaf(d, d, acc0);
        d = a1.x - b1.x; acc1 = fmaf(d, d, acc1);
        d = a1.y - b1.y; acc1 = fmaf(d, d, acc1);
        d = a1.z - b1.z; acc1 = fmaf(d, d, acc1);
        d = a1.w - b1.w; acc1 = fmaf(d, d, acc1);
    }
    // Remainder (at most one strided element per thread).
    for (; i < Sv; i += stride) {
        float4 a = __ldg(&r[i]);
        float4 b = __ldg(&s[i]);
        float d;
        d = a.x - b.x; acc0 = fmaf(d, d, acc0);
        d = a.y - b.y; acc0 = fmaf(d, d, acc0);
        d = a.z - b.z; acc0 = fmaf(d, d, acc0);
        d = a.w - b.w; acc0 = fmaf(d, d, acc0);
    }
    float acc = acc0 + acc1;

    __shared__ float warp_sums[8];
    #pragma unroll
    for (int off = 16; off; off >>= 1)
        acc += __shfl_down_sync(0xffffffffu, acc, off);
    int lane = threadIdx.x & 31;
    int wid  = threadIdx.x >> 5;
    if (lane == 0) warp_sums[wid] = acc;
    __syncthreads();
    if (threadIdx.x == 0) {
        float t = 0.0f;
        int nwarps = blockDim.x >> 5;
        #pragma unroll 8
        for (int w = 0; w < nwarps; w++) t += warp_sums[w];
        out[row] = t * scale + g_prior;
    }
}

extern "C" void kernel_launch(void* const* d_in, const int* in_sizes, int n_in,
                              void* d_out, int out_size) {
    const float* pred  = (const float*)d_in[0];   // [B,7]
    const float* sigma = (const float*)d_in[1];   // [B,7]
    const float* yR    = (const float*)d_in[2];   // [B,S]
    const float* yS    = (const float*)d_in[3];   // [B,S]
    float* out = (float*)d_out;                   // [B]

    int B = in_sizes[0] / 7;
    int S = in_sizes[2] / B;
    int Sv = S / 4;                               // S=4096 -> 1024 float4/row
    // likelihood = mse / (2 * 0.1^2) = (sum/S) * 50
    float scale = 50.0f / (float)S;

    prior_kernel<<<1, 1024>>>(pred, sigma, B);
    mse_posterior_kernel<<<B, 256>>>((const float4*)yR, (const float4*)yS,
                                     out, Sv, scale);
}

// round 4
// speedup vs baseline: 1.4081x; 1.4081x over previous
#include <cuda_runtime.h>

#define LOG_SQRT_2PI 0.9189385332046727f
#define PRIOR_BLOCKS 32

// Per-block partial sums of the prior, written by prior_kernel,
// folded by every mse block's epilogue (one L2-resident 128B line).
__device__ float g_prior_partials[PRIOR_BLOCKS];

// ---------------------------------------------------------------------------
// Kernel A: parallel prior partial sums.
// 32 blocks x 256 threads = 8192 threads -> 1 row/thread at B=8192.
// ---------------------------------------------------------------------------
__global__ void prior_kernel(const float* __restrict__ pred,
                             const float* __restrict__ sigma,
                             int B) {
    float acc = 0.0f;
    int nthreads = gridDim.x * blockDim.x;
    for (int row = blockIdx.x * blockDim.x + threadIdx.x; row < B; row += nthreads) {
        const float* p = pred + (size_t)row * 7;
        float O2  = p[0], N2 = p[1], H2 = p[2], CO2 = p[3];
        float H2O = p[4], CH4 = p[5], NH3 = p[6];

        float H = 2.0f*H2 + 2.0f*H2O + 3.0f*NH3 + 4.0f*CH4;
        float C = CO2 + CH4;
        float O = 2.0f*O2 + 2.0f*CO2 + H2O;
        float N = 2.0f*N2 + NH3;

        float mu0=0.f, mu1=0.f, mu2=0.f, mu3=0.f, mu4=0.f, mu5=0.f, mu6=0.f;

        bool condA = (H > 2.0f*O + 4.0f*C);
        if (condA) {
            if (3.0f*N < H - 2.0f*O - 4.0f*C) {
                // branch A1: D = H - N - 2C
                float inv = 1.0f / (H - N - 2.0f*C);
                mu2 = (H - 2.0f*O - 4.0f*C - 3.0f*N) * inv;
                mu4 = 2.0f*O * inv;
                mu5 = 2.0f*C * inv;
                mu6 = 2.0f*N * inv;
            } else {
                // branch A2: D = H + 2C + 3N + 4O
                float inv = 1.0f / (H + 2.0f*C + 3.0f*N + 4.0f*O);
                mu1 = (3.0f*N + 4.0f*C + 2.0f*O - H) * inv;
                mu4 = 6.0f*O * inv;
                mu5 = 6.0f*C * inv;
                mu6 = (2.0f*H - 8.0f*C - 4.0f*O) * inv;
            }
        } else if (2.0f*O > H + 4.0f*C) {
            // branch B: D = H + 2O + 2N
            float inv = 1.0f / (H + 2.0f*O + 2.0f*N);
            mu0 = (2.0f*O - H - 4.0f*C) * inv;
            mu1 = 2.0f*N * inv;
            mu3 = 4.0f*C * inv;
            mu4 = 2.0f*H * inv;
        } else if (fabsf(H + C + O + N - 1.0f) < 1e-3f) {
            // branch C: D1 = H + 2O + 2N, D2 = 2H + 4O + 4N
            float inv1 = 1.0f / (H + 2.0f*O + 2.0f*N);
            float inv2 = 1.0f / (2.0f*H + 4.0f*O + 4.0f*N);
            mu1 = 2.0f*N * inv1;
            mu3 = (2.0f*O + 4.0f*C - H) * inv2;
            mu4 = (H + 2.0f*O - 4.0f*C) * inv1;
            mu5 = (H - 2.0f*O + 4.0f*C) * inv2;
        }
        // else: unclassified -> mu = 0

        const float* s = sigma + (size_t)row * 7;
        float mu[7] = {mu0, mu1, mu2, mu3, mu4, mu5, mu6};
        #pragma unroll
        for (int i = 0; i < 7; i++) {
            float sg = s[i];
            float d  = p[i] - mu[i];
            acc += LOG_SQRT_2PI + __logf(sg) + d*d / (2.0f * sg * sg);
        }
    }

    // Block reduction: warp shuffle -> smem -> warp shuffle
    __shared__ float warp_sums[8];
    #pragma unroll
    for (int off = 16; off; off >>= 1)
        acc += __shfl_down_sync(0xffffffffu, acc, off);
    int lane = threadIdx.x & 31;
    int wid  = threadIdx.x >> 5;
    if (lane == 0) warp_sums[wid] = acc;
    __syncthreads();
    if (wid == 0) {
        int nwarps = blockDim.x >> 5;
        acc = (lane < nwarps) ? warp_sums[lane] : 0.0f;
        #pragma unroll
        for (int off = 16; off; off >>= 1)
            acc += __shfl_down_sync(0xffffffffu, acc, off);
        if (lane == 0) g_prior_partials[blockIdx.x] = acc;
    }
}

// ---------------------------------------------------------------------------
// Kernel B: one block (256 threads) per batch row. Streaming MSE.
// Specialized path for Sv==1024: each thread owns exactly 4 float4 per input;
// all 8 LDG.128 issued up front (__ldcs: read-once, evict-first).
// Epilogue folds the 32 prior partials (L2-broadcast line) into the output.
// ---------------------------------------------------------------------------
__global__ void mse_posterior_kernel(const float4* __restrict__ yR,
                                     const float4* __restrict__ yS,
                                     float* __restrict__ out,
                                     int Sv,        // S / 4 (# of float4 per row)
                                     float scale,   // 50 / S
                                     float invB) {  // 1 / B
    int row = blockIdx.x;
    const float4* r = yR + (size_t)row * Sv;
    const float4* s = yS + (size_t)row * Sv;

    float acc = 0.0f;
    if (Sv == 1024 && blockDim.x == 256) {
        // Fully unrolled: 4 float4 per array per thread, 8 independent LDG.128.
        int t = threadIdx.x;
        float4 a0 = __ldcs(&r[t]);
        float4 a1 = __ldcs(&r[t + 256]);
        float4 a2 = __ldcs(&r[t + 512]);
        float4 a3 = __ldcs(&r[t + 768]);
        float4 b0 = __ldcs(&s[t]);
        float4 b1 = __ldcs(&s[t + 256]);
        float4 b2 = __ldcs(&s[t + 512]);
        float4 b3 = __ldcs(&s[t + 768]);
        float d;
        float p0 = 0.f, p1 = 0.f, p2 = 0.f, p3 = 0.f;
        d = a0.x-b0.x; p0 = fmaf(d,d,p0);  d = a0.y-b0.y; p0 = fmaf(d,d,p0);
        d = a0.z-b0.z; p0 = fmaf(d,d,p0);  d = a0.w-b0.w; p0 = fmaf(d,d,p0);
        d = a1.x-b1.x; p1 = fmaf(d,d,p1);  d = a1.y-b1.y; p1 = fmaf(d,d,p1);
        d = a1.z-b1.z; p1 = fmaf(d,d,p1);  d = a1.w-b1.w; p1 = fmaf(d,d,p1);
        d = a2.x-b2.x; p2 = fmaf(d,d,p2);  d = a2.y-b2.y; p2 = fmaf(d,d,p2);
        d = a2.z-b2.z; p2 = fmaf(d,d,p2);  d = a2.w-b2.w; p2 = fmaf(d,d,p2);
        d = a3.x-b3.x; p3 = fmaf(d,d,p3);  d = a3.y-b3.y; p3 = fmaf(d,d,p3);
        d = a3.z-b3.z; p3 = fmaf(d,d,p3);  d = a3.w-b3.w; p3 = fmaf(d,d,p3);
        acc = (p0 + p1) + (p2 + p3);
    } else {
        // Generic fallback (unrolled x2, dual accumulators).
        float acc0 = 0.0f, acc1 = 0.0f;
        int stride = blockDim.x;
        int i = threadIdx.x;
        for (; i + stride < Sv; i += 2 * stride) {
            float4 a0 = __ldcs(&r[i]);
            float4 b0 = __ldcs(&s[i]);
            float4 a1 = __ldcs(&r[i + stride]);
            float4 b1 = __ldcs(&s[i + stride]);
            float d;
            d = a0.x-b0.x; acc0 = fmaf(d,d,acc0);  d = a0.y-b0.y; acc0 = fmaf(d,d,acc0);
            d = a0.z-b0.z; acc0 = fmaf(d,d,acc0);  d = a0.w-b0.w; acc0 = fmaf(d,d,acc0);
            d = a1.x-b1.x; acc1 = fmaf(d,d,acc1);  d = a1.y-b1.y; acc1 = fmaf(d,d,acc1);
            d = a1.z-b1.z; acc1 = fmaf(d,d,acc1);  d = a1.w-b1.w; acc1 = fmaf(d,d,acc1);
        }
        for (; i < Sv; i += stride) {
            float4 a = __ldcs(&r[i]);
            float4 b = __ldcs(&s[i]);
            float d;
            d = a.x-b.x; acc0 = fmaf(d,d,acc0);  d = a.y-b.y; acc0 = fmaf(d,d,acc0);
            d = a.z-b.z; acc0 = fmaf(d,d,acc0);  d = a.w-b.w; acc0 = fmaf(d,d,acc0);
        }
        acc = acc0 + acc1;
    }

    __shared__ float warp_sums[8];
    #pragma unroll
    for (int off = 16; off; off >>= 1)
        acc += __shfl_down_sync(0xffffffffu, acc, off);
    int lane = threadIdx.x & 31;
    int wid  = threadIdx.x >> 5;
    if (lane == 0) warp_sums[wid] = acc;
    __syncthreads();

    if (wid == 0) {
        // Fold the 32 prior partials with warp 0 (PRIOR_BLOCKS == 32 == warp size).
        float pp = g_prior_partials[lane];
        #pragma unroll
        for (int off = 16; off; off >>= 1)
            pp += __shfl_down_sync(0xffffffffu, pp, off);

        if (lane == 0) {
            float t = 0.0f;
            int nwarps = blockDim.x >> 5;
            #pragma unroll 8
            for (int w = 0; w < nwarps; w++) t += warp_sums[w];
            out[row] = t * scale + pp * invB;
        }
    }
}

extern "C" void kernel_launch(void* const* d_in, const int* in_sizes, int n_in,
                              void* d_out, int out_size) {
    const float* pred  = (const float*)d_in[0];   // [B,7]
    const float* sigma = (const float*)d_in[1];   // [B,7]
    const float* yR    = (const float*)d_in[2];   // [B,S]
    const float* yS    = (const float*)d_in[3];   // [B,S]
    float* out = (float*)d_out;                   // [B]

    int B = in_sizes[0] / 7;
    int S = in_sizes[2] / B;
    int Sv = S / 4;                               // S=4096 -> 1024 float4/row
    float scale = 50.0f / (float)S;               // likelihood scale
    float invB  = 1.0f / (float)B;

    prior_kernel<<<PRIOR_BLOCKS, 256>>>(pred, sigma, B);
    mse_posterior_kernel<<<B, 256>>>((const float4*)yR, (const float4*)yS,
                                     out, Sv, scale, invB);
}